// round 14
// baseline (speedup 1.0000x reference)
#include <cuda_runtime.h>
#include <cuda_bf16.h>
#include <type_traits>

// Problem shape constants (fixed by setup_inputs)
#define B_  2
#define HI  64
#define WI  64
#define DI  32
#define CC  16
#define FF  8
#define HO  128
#define WO  128
#define DO_ 64

// Padded weight tap: 8 filters * 16 ch * 4B = 512B, +16B pad between filter
// halves so (fg,cg) lane groups hit disjoint bank spans. Stride = 528 B.
#define TAPB 528

typedef unsigned long long u64;

// ---- packed f32x2 helpers (sm_100+; ptxas never emits these from C++) ----
__device__ __forceinline__ u64 fma2(u64 a, u64 b, u64 c) {
    u64 d;
    asm("fma.rn.f32x2 %0, %1, %2, %3;" : "=l"(d) : "l"(a), "l"(b), "l"(c));
    return d;
}
__device__ __forceinline__ u64 add2(u64 a, u64 b) {
    u64 d;
    asm("add.rn.f32x2 %0, %1, %2;" : "=l"(d) : "l"(a), "l"(b));
    return d;
}
__device__ __forceinline__ void ldg128(u64& a, u64& b, const float* p) {
    asm("ld.global.nc.v2.b64 {%0, %1}, [%2];" : "=l"(a), "=l"(b) : "l"(p));
}
__device__ __forceinline__ void lds128(u64& a, u64& b, unsigned addr) {
    asm("ld.shared.v2.b64 {%0, %1}, [%2];" : "=l"(a), "=l"(b) : "r"(addr));
}
__device__ __forceinline__ u64 pack2(float x) {
    u64 d;
    asm("mov.b64 %0, {%1, %1};" : "=l"(d) : "f"(x));
    return d;
}
__device__ __forceinline__ float lo32(u64 a) { return __uint_as_float((unsigned)a); }
__device__ __forceinline__ float hi32(u64 a) { return __uint_as_float((unsigned)(a >> 32)); }

// Load one depth-row slice for this lane: 8 floats = 4 u64 (32 B), or default.
__device__ __forceinline__ void load_row8(u64 r[4], const float* p, bool ok, u64 dv2) {
    if (ok) { ldg128(r[0], r[1], p); ldg128(r[2], r[3], p + 4); }
    else    { r[0] = dv2; r[1] = dv2; r[2] = dv2; r[3] = dv2; }
}

// One input pixel's depth taps. Lane owns 8 channels (cg), 4 filters (fg),
// 4 depth slabs (g: s = 4g+j).
// MODD=true : taps kd=0 & kd=2. Slab j: row (r0+j) w/ kd0, row (r0+j-1) w/ kd2
//             -> 5-row window rows[t] = r0-1+t.
// MODD=false: tap kd=1. Slab j: row (r0+j) -> 4-row window.
// wbhw = smem weight base for (kh,kw,kd=0) incl. lane's (fg,cg) offset.
template<bool MODD>
__device__ __forceinline__ void pixel_taps(const float* __restrict__ irow,
                                           unsigned wbhw, int r0, u64 dv2,
                                           u64 (*acc)[4])
{
    if (MODD) {
        u64 rows[5][4];
        const float* p = irow + (long)(r0 - 1) * CC;
        #pragma unroll
        for (int t = 0; t < 5; t++)
            load_row8(rows[t], p + t * CC, (unsigned)(r0 - 1 + t) < DI, dv2);
        const unsigned wb0 = wbhw;                // kd = 0 weights
        const unsigned wb2 = wbhw + 2 * TAPB;     // kd = 2 weights
        #pragma unroll
        for (int f = 0; f < 4; f++) {
            u64 w[4], x[4];
            lds128(w[0], w[1], wb0 + f * 64);
            lds128(w[2], w[3], wb0 + f * 64 + 16);
            lds128(x[0], x[1], wb2 + f * 64);
            lds128(x[2], x[3], wb2 + f * 64 + 16);
            #pragma unroll
            for (int j = 0; j < 4; j++) {
                #pragma unroll
                for (int q = 0; q < 4; q++) {
                    acc[f][j] = fma2(rows[j + 1][q], w[q], acc[f][j]);
                    acc[f][j] = fma2(rows[j][q],     x[q], acc[f][j]);
                }
            }
        }
    } else {
        u64 rows[4][4];
        const float* p = irow + (long)r0 * CC;
        #pragma unroll
        for (int t = 0; t < 4; t++)
            load_row8(rows[t], p + t * CC, (unsigned)(r0 + t) < DI, dv2);
        const unsigned wb1 = wbhw + TAPB;         // kd = 1 weights
        #pragma unroll
        for (int f = 0; f < 4; f++) {
            u64 w[4];
            lds128(w[0], w[1], wb1 + f * 64);
            lds128(w[2], w[3], wb1 + f * 64 + 16);
            #pragma unroll
            for (int j = 0; j < 4; j++) {
                #pragma unroll
                for (int q = 0; q < 4; q++)
                    acc[f][j] = fma2(rows[j][q], w[q], acc[f][j]);
            }
        }
    }
}

// Block: 256 threads = 8 warps. Warp w: wo = blockIdx.x*4 + w/2, parity = w&1.
// Lane = g*4 + fg*2 + cg: cg owns channels [cg*8, cg*8+8), fg owns filters
// [fg*4, fg*4+4), g owns depth slabs 4g..4g+3 (douts 2s+par). Valid taps are
// precomputed from the three warp-uniform parity bits. Channel reduction is a
// single shfl_xor(1); afterwards lane keeps slabs j in {2cg, 2cg+1}.
__global__ __launch_bounds__(256, 2)
void sparse_conv3d_transpose_kernel(const float* __restrict__ images,
                                    const int*   __restrict__ base_plane,
                                    const float* __restrict__ kernel,
                                    const float* __restrict__ defv,
                                    float*       __restrict__ out)
{
    __shared__ __align__(16) float sw[27 * TAPB / 4];   // 14256 B (padded taps)
    // repack [tap][f][c] -> tap*132 + f*16 + (f>>2)*4 + c   (float units)
    for (int i = threadIdx.x; i < 27 * FF * CC; i += 256) {
        const int tap = i >> 7;            // /128
        const int f   = (i >> 4) & 7;
        const int c   = i & 15;
        sw[tap * (TAPB / 4) + f * 16 + (f >> 2) * 4 + c] = kernel[i];
    }
    __syncthreads();

    const int b    = blockIdx.z;
    const int ho   = blockIdx.y;
    const int warp = threadIdx.x >> 5;
    const int lane = threadIdx.x & 31;
    const int wo   = (blockIdx.x << 2) + (warp >> 1);
    const int par  = warp & 1;
    const int cg   = lane & 1;
    const int fg   = (lane >> 1) & 1;
    const int g    = lane >> 2;

    const u64 dv2 = pack2(*defv);
    const int bpv = __ldg(base_plane + (b * HO + ho) * WO + wo);
    const int m   = bpv + par;

    // swbase folds in this lane's (fg, cg) weight offset (fg stride incl. pad).
    const unsigned swbase = (unsigned)__cvta_generic_to_shared(sw)
                          + (unsigned)(fg * (4 * 64 + 16) + cg * 32);

    u64 acc[4][4];   // [f-local][j] : partials over this lane's 8 channels
    #pragma unroll
    for (int f = 0; f < 4; f++)
        #pragma unroll
        for (int j = 0; j < 4; j++) acc[f][j] = 0ull;

    // --- precompute valid spatial taps (warp-uniform, <=2 each) ---
    int hi0, hi1 = 0, nh;
    unsigned wbh0, wbh1 = 0;                       // kh * 9 * TAPB
    if (ho & 1) {
        if (ho == HO - 1) { nh = 1; hi0 = (ho - 1) >> 1; wbh0 = 2u * 9 * TAPB; }
        else { nh = 2; hi0 = (ho + 1) >> 1; wbh0 = 0;
               hi1 = (ho - 1) >> 1; wbh1 = 2u * 9 * TAPB; }
    } else { nh = 1; hi0 = ho >> 1; wbh0 = 1u * 9 * TAPB; }

    int wi0, wi1 = 0, nw;
    unsigned wbw0, wbw1 = 0;                       // kw * 3 * TAPB
    if (wo & 1) {
        if (wo == WO - 1) { nw = 1; wi0 = (wo - 1) >> 1; wbw0 = 2u * 3 * TAPB; }
        else { nw = 2; wi0 = (wo + 1) >> 1; wbw0 = 0;
               wi1 = (wo - 1) >> 1; wbw1 = 2u * 3 * TAPB; }
    } else { nw = 1; wi0 = wo >> 1; wbw0 = 1u * 3 * TAPB; }

    auto spatial = [&](auto modd_c) {
        constexpr bool MODD = decltype(modd_c)::value;
        const int off = MODD ? ((m + 1) >> 1) : (m >> 1);
        #pragma unroll 1
        for (int a = 0; a < nh; a++) {
            const int hi       = a ? hi1 : hi0;
            const unsigned wbh = a ? wbh1 : wbh0;
            const int bprow    = (b * HO + (hi << 1)) * WO;
            const float* hrow  = images + (size_t)((b * HI + hi) * WI) * DI * CC;
            #pragma unroll 1
            for (int c = 0; c < nw; c++) {
                const int wi       = c ? wi1 : wi0;
                const unsigned wbw = c ? wbw1 : wbw0;
                const int bpg = __ldg(base_plane + bprow + (wi << 1)) >> 1;
                const float* irow = hrow + (size_t)wi * DI * CC + cg * 8;
                const int r0 = 4 * g + off - bpg;
                pixel_taps<MODD>(irow, swbase + wbh + wbw, r0, dv2, acc);
            }
        }
    };

    if (m & 1) spatial(std::integral_constant<bool, true>{});
    else       spatial(std::integral_constant<bool, false>{});

    // Reduce across the cg pair (other 8 channels); lane keeps slabs 2cg,2cg+1.
    #pragma unroll
    for (int f = 0; f < 4; f++)
        #pragma unroll
        for (int j = 0; j < 4; j++)
            acc[f][j] = add2(acc[f][j], __shfl_xor_sync(0xffffffffu, acc[f][j], 1));

    const size_t obase = ((size_t)((b * HO + ho) * WO + wo)) * DO_;
    #pragma unroll
    for (int jj = 0; jj < 2; jj++) {
        const int j    = 2 * cg + jj;
        const int dout = 2 * (4 * g + j) + par;
        float4 v;
        v.x = lo32(acc[0][j]) + hi32(acc[0][j]);
        v.y = lo32(acc[1][j]) + hi32(acc[1][j]);
        v.z = lo32(acc[2][j]) + hi32(acc[2][j]);
        v.w = lo32(acc[3][j]) + hi32(acc[3][j]);
        *(float4*)(out + (obase + dout) * FF + fg * 4) = v;
    }
}

extern "C" void kernel_launch(void* const* d_in, const int* in_sizes, int n_in,
                              void* d_out, int out_size)
{
    const float* images     = (const float*)d_in[0];   // [2,64,64,32,16] f32
    const int*   base_plane = (const int*)  d_in[1];   // [2,128,128,1] i32
    const float* kern       = (const float*)d_in[2];   // [3,3,3,8,16] f32
    const float* defv       = (const float*)d_in[3];   // scalar f32 (zero)
    float*       out        = (float*)d_out;           // [2,128,128,64,8] f32

    dim3 grid(WO / 4, HO, B_);
    sparse_conv3d_transpose_kernel<<<grid, 256>>>(images, base_plane, kern, defv, out);
}